// round 16
// baseline (speedup 1.0000x reference)
#include <cuda_runtime.h>
#include <cuda_fp16.h>
#include <stdint.h>
#include <math.h>

#define NTOK 4096
#define DIM 1024
#define NHEADS 16
#define HD 64
#define QKV_N 3072
#define SCALE 0.125f   // 1/sqrt(64)

// ---------------- scratch (no allocations allowed) ----------------
__device__ float  g_qkv[NTOK * QKV_N];
__device__ float  g_Q[NHEADS * NTOK * HD];
__device__ __half g_Kh[NHEADS * NTOK * HD];
__device__ __half g_Vh[NHEADS * NTOK * HD];
__device__ float  g_attn[NTOK * DIM];

__device__ __forceinline__ uint32_t cvt_tf32(float x) {
    uint32_t r;
    asm("cvt.rna.tf32.f32 %0, %1;" : "=r"(r) : "f"(x));
    return r;
}

__device__ __forceinline__ uint32_t f2h2(float a, float b) {
    __half2 h = __floats2half2_rn(a, b);
    return *(uint32_t*)&h;
}

__device__ __forceinline__ void mma_tf32(float& c0, float& c1, float& c2, float& c3,
                                         uint32_t a0, uint32_t a1, uint32_t a2, uint32_t a3,
                                         uint32_t b0, uint32_t b1) {
    asm volatile(
        "mma.sync.aligned.m16n8k8.row.col.f32.tf32.tf32.f32 "
        "{%0,%1,%2,%3}, {%4,%5,%6,%7}, {%8,%9}, {%0,%1,%2,%3};"
        : "+f"(c0), "+f"(c1), "+f"(c2), "+f"(c3)
        : "r"(a0), "r"(a1), "r"(a2), "r"(a3), "r"(b0), "r"(b1));
}

__device__ __forceinline__ void mma_f16(float& c0, float& c1, float& c2, float& c3,
                                        uint32_t a0, uint32_t a1, uint32_t a2, uint32_t a3,
                                        uint32_t b0, uint32_t b1) {
    asm volatile(
        "mma.sync.aligned.m16n8k16.row.col.f32.f16.f16.f32 "
        "{%0,%1,%2,%3}, {%4,%5,%6,%7}, {%8,%9}, {%0,%1,%2,%3};"
        : "+f"(c0), "+f"(c1), "+f"(c2), "+f"(c3)
        : "r"(a0), "r"(a1), "r"(a2), "r"(a3), "r"(b0), "r"(b1));
}

__device__ __forceinline__ void ldsm_x4(uint32_t& r0, uint32_t& r1,
                                        uint32_t& r2, uint32_t& r3, uint32_t saddr) {
    asm volatile("ldmatrix.sync.aligned.m8n8.x4.shared.b16 {%0,%1,%2,%3}, [%4];"
                 : "=r"(r0), "=r"(r1), "=r"(r2), "=r"(r3) : "r"(saddr));
}

__device__ __forceinline__ void ldsm_x4t(uint32_t& r0, uint32_t& r1,
                                         uint32_t& r2, uint32_t& r3, uint32_t saddr) {
    asm volatile("ldmatrix.sync.aligned.m8n8.x4.trans.shared.b16 {%0,%1,%2,%3}, [%4];"
                 : "=r"(r0), "=r"(r1), "=r"(r2), "=r"(r3) : "r"(saddr));
}

__device__ __forceinline__ void cp_async16(uint32_t saddr, const void* gptr) {
    asm volatile("cp.async.cg.shared.global [%0], [%1], 16;"
                 :: "r"(saddr), "l"(gptr));
}
__device__ __forceinline__ void cp_commit() {
    asm volatile("cp.async.commit_group;");
}
__device__ __forceinline__ void cp_wait0() {
    asm volatile("cp.async.wait_group 0;");
}

// ---------------- tf32 MMA GEMM with register-prefetch pipeline (85us) ------
#define GBM 128
#define GBN 128
#define GBK 16
#define GST 136

__global__ __launch_bounds__(256, 2) void gemm_tf32_kernel(
    const float* __restrict__ A, const float* __restrict__ B,
    const float* __restrict__ bias, float* __restrict__ C,
    int M, int N, int K)
{
    __shared__ float Ast[GBK][GST];
    __shared__ float Bs[GBK][GST];

    const int tid = threadIdx.x;
    const int wid = tid >> 5;
    const int lane = tid & 31;
    const int qr = lane >> 2;
    const int qc = lane & 3;
    const int wm = wid >> 2;
    const int wn = wid & 3;
    const int rowBase = blockIdx.y * GBM;
    const int colBase = blockIdx.x * GBN;

    int ar[2], ac[2], br[2], bc[2];
    #pragma unroll
    for (int i = 0; i < 2; i++) {
        int v = tid + i * 256;
        ar[i] = v >> 2;  ac[i] = (v & 3) * 4;
        br[i] = v >> 5;  bc[i] = (v & 31) * 4;
    }

    float acc[4][4][4];
    #pragma unroll
    for (int mi = 0; mi < 4; mi++)
        #pragma unroll
        for (int ni = 0; ni < 4; ni++)
            #pragma unroll
            for (int r = 0; r < 4; r++) acc[mi][ni][r] = 0.f;

    float4 pa[2], pb[2];
    #pragma unroll
    for (int i = 0; i < 2; i++) {
        pa[i] = *(const float4*)&A[(size_t)(rowBase + ar[i]) * K + ac[i]];
        pb[i] = *(const float4*)&B[(size_t)br[i] * N + colBase + bc[i]];
    }

    for (int k0 = 0; k0 < K; k0 += GBK) {
        #pragma unroll
        for (int i = 0; i < 2; i++) {
            Ast[ac[i] + 0][ar[i]] = __uint_as_float(cvt_tf32(pa[i].x));
            Ast[ac[i] + 1][ar[i]] = __uint_as_float(cvt_tf32(pa[i].y));
            Ast[ac[i] + 2][ar[i]] = __uint_as_float(cvt_tf32(pa[i].z));
            Ast[ac[i] + 3][ar[i]] = __uint_as_float(cvt_tf32(pa[i].w));
            float4 g;
            g.x = __uint_as_float(cvt_tf32(pb[i].x));
            g.y = __uint_as_float(cvt_tf32(pb[i].y));
            g.z = __uint_as_float(cvt_tf32(pb[i].z));
            g.w = __uint_as_float(cvt_tf32(pb[i].w));
            *(float4*)&Bs[br[i]][bc[i]] = g;
        }
        __syncthreads();

        if (k0 + GBK < K) {
            #pragma unroll
            for (int i = 0; i < 2; i++) {
                pa[i] = *(const float4*)&A[(size_t)(rowBase + ar[i]) * K + (k0 + GBK) + ac[i]];
                pb[i] = *(const float4*)&B[(size_t)(k0 + GBK + br[i]) * N + colBase + bc[i]];
            }
        }

        #pragma unroll
        for (int kk = 0; kk < 2; kk++) {
            uint32_t af[4][4], bf[4][2];
            #pragma unroll
            for (int mi = 0; mi < 4; mi++) {
                int m = wm * 64 + mi * 16;
                af[mi][0] = __float_as_uint(Ast[kk * 8 + qc]    [m + qr]);
                af[mi][1] = __float_as_uint(Ast[kk * 8 + qc]    [m + qr + 8]);
                af[mi][2] = __float_as_uint(Ast[kk * 8 + qc + 4][m + qr]);
                af[mi][3] = __float_as_uint(Ast[kk * 8 + qc + 4][m + qr + 8]);
            }
            #pragma unroll
            for (int ni = 0; ni < 4; ni++) {
                int n = wn * 32 + ni * 8;
                bf[ni][0] = __float_as_uint(Bs[kk * 8 + qc]    [n + qr]);
                bf[ni][1] = __float_as_uint(Bs[kk * 8 + qc + 4][n + qr]);
            }
            #pragma unroll
            for (int mi = 0; mi < 4; mi++)
                #pragma unroll
                for (int ni = 0; ni < 4; ni++)
                    mma_tf32(acc[mi][ni][0], acc[mi][ni][1], acc[mi][ni][2], acc[mi][ni][3],
                             af[mi][0], af[mi][1], af[mi][2], af[mi][3],
                             bf[ni][0], bf[ni][1]);
        }
        __syncthreads();
    }

    #pragma unroll
    for (int mi = 0; mi < 4; mi++) {
        int m = rowBase + wm * 64 + mi * 16;
        #pragma unroll
        for (int ni = 0; ni < 4; ni++) {
            int n = colBase + wn * 32 + ni * 8 + 2 * qc;
            float bx = bias[n], by = bias[n + 1];
            float2 w0, w1;
            w0.x = acc[mi][ni][0] + bx;  w0.y = acc[mi][ni][1] + by;
            w1.x = acc[mi][ni][2] + bx;  w1.y = acc[mi][ni][3] + by;
            *(float2*)&C[(size_t)(m + qr) * N + n] = w0;
            *(float2*)&C[(size_t)(m + qr + 8) * N + n] = w1;
        }
    }
}

// ---------------- RoPE + split: Q fp32, K/V fp16 ----------------
__global__ void rope_split_kernel(const float* __restrict__ cosb,
                                  const float* __restrict__ sinb)
{
    int idx = blockIdx.x * blockDim.x + threadIdx.x;
    if (idx >= NTOK * NHEADS * 32) return;
    int d = idx & 31;
    int h = (idx >> 5) & 15;
    int n = idx >> 9;

    const float* base = g_qkv + (size_t)n * QKV_N;
    float c = cosb[n * 32 + d];
    float s = sinb[n * 32 + d];

    size_t ho = ((size_t)h * NTOK + n) * HD;

    float x1 = base[h * HD + d];
    float x2 = base[h * HD + d + 32];
    g_Q[ho + d]      = x1 * c - x2 * s;
    g_Q[ho + d + 32] = x2 * c + x1 * s;

    float y1 = base[DIM + h * HD + d];
    float y2 = base[DIM + h * HD + d + 32];
    g_Kh[ho + d]      = __float2half(y1 * c - y2 * s);
    g_Kh[ho + d + 32] = __float2half(y2 * c + y1 * s);

    g_Vh[ho + d]      = __float2half(base[2 * DIM + h * HD + d]);
    g_Vh[ho + d + 32] = __float2half(base[2 * DIM + h * HD + d + 32]);
}

// ---------------- flash attention: fp16 mma + cp.async double buffer -------
#define ATT_BQ 128
#define H2ST 36            // half2 words per row (32 data + 4 pad)
#define H2STB 144          // bytes
#define KVBUF (64 * H2ST)  // words per K or V buffer

__global__ __launch_bounds__(256) void attn_mma_kernel()
{
    extern __shared__ uint32_t sm2[];
    // [buf0: K,V][buf1: K,V][P]
    uint32_t* Ps2 = sm2 + 4 * KVBUF;

    const int tid = threadIdx.x;
    const int h = blockIdx.y;
    const int q0 = blockIdx.x * ATT_BQ;
    const int wid = tid >> 5;
    const int lane = tid & 31;
    const int qr = lane >> 2;
    const int qc = lane & 3;

    const uint32_t sm_base = (uint32_t)__cvta_generic_to_shared(sm2);
    const uint32_t ps_base = sm_base + 4 * KVBUF * 4;

    // fragment lane offsets (relative to each buffer's K/V base)
    const uint32_t ks_lane_off = (((lane >> 4) & 1) * 8 + (lane & 7)) * H2STB
                               + ((lane >> 3) & 1) * 16;
    const uint32_t vs_lane_off = (((lane >> 3) & 1) * 8 + (lane & 7)) * H2STB
                               + ((lane >> 4) & 1) * 16;
    const uint32_t ps_lane = ps_base + (wid * 16 + ((lane >> 4) & 1) * 8 + (lane & 7)) * H2STB
                               + ((lane >> 3) & 1) * 16;

    // cp.async per-thread chunk coords: 512 16B-chunks per matrix, 2/thread
    // chunk: r = v>>3 (row), c16 = v&7 (16B column)
    const int cv0 = tid, cv1 = tid + 256;
    const int cr0 = cv0 >> 3, cc0 = cv0 & 7;
    const int cr1 = cv1 >> 3, cc1 = cv1 & 7;

    const float* qbase = g_Q + ((size_t)h * NTOK + q0 + wid * 16) * HD;
    uint32_t qf[4][4];
    #pragma unroll
    for (int kk = 0; kk < 4; kk++) {
        int k0 = kk * 16 + 2 * qc;
        qf[kk][0] = f2h2(qbase[(size_t)qr       * HD + k0]     * SCALE,
                         qbase[(size_t)qr       * HD + k0 + 1] * SCALE);
        qf[kk][1] = f2h2(qbase[(size_t)(qr + 8) * HD + k0]     * SCALE,
                         qbase[(size_t)(qr + 8) * HD + k0 + 1] * SCALE);
        qf[kk][2] = f2h2(qbase[(size_t)qr       * HD + k0 + 8] * SCALE,
                         qbase[(size_t)qr       * HD + k0 + 9] * SCALE);
        qf[kk][3] = f2h2(qbase[(size_t)(qr + 8) * HD + k0 + 8] * SCALE,
                         qbase[(size_t)(qr + 8) * HD + k0 + 9] * SCALE);
    }

    float m0 = -1e30f, m1 = -1e30f, l0 = 0.f, l1 = 0.f;
    float o[8][4];
    #pragma unroll
    for (int nb = 0; nb < 8; nb++)
        #pragma unroll
        for (int r = 0; r < 4; r++) o[nb][r] = 0.f;

    const __half* kb = g_Kh + (size_t)h * NTOK * HD;
    const __half* vb = g_Vh + (size_t)h * NTOK * HD;

    // prefetch tile 0 into buffer 0
    {
        uint32_t kdst = sm_base;            // buf0 K
        uint32_t vdst = sm_base + KVBUF * 4;
        cp_async16(kdst + cr0 * H2STB + cc0 * 16, kb + (size_t)cr0 * HD + cc0 * 8);
        cp_async16(kdst + cr1 * H2STB + cc1 * 16, kb + (size_t)cr1 * HD + cc1 * 8);
        cp_async16(vdst + cr0 * H2STB + cc0 * 16, vb + (size_t)cr0 * HD + cc0 * 8);
        cp_async16(vdst + cr1 * H2STB + cc1 * 16, vb + (size_t)cr1 * HD + cc1 * 8);
        cp_commit();
    }

    #pragma unroll 1
    for (int t = 0; t < NTOK; t += 64) {
        const int buf = (t >> 6) & 1;
        const uint32_t kbase = sm_base + buf * 2 * KVBUF * 4;
        const uint32_t vbase = kbase + KVBUF * 4;

        cp_wait0();
        __syncthreads();     // tile ready; all warps done with prior buf reads

        // prefetch next tile into the other buffer (overlaps compute below)
        if (t + 64 < NTOK) {
            const uint32_t nk = sm_base + (buf ^ 1) * 2 * KVBUF * 4;
            const uint32_t nv = nk + KVBUF * 4;
            const __half* ksrc = kb + (size_t)(t + 64) * HD;
            const __half* vsrc = vb + (size_t)(t + 64) * HD;
            cp_async16(nk + cr0 * H2STB + cc0 * 16, ksrc + (size_t)cr0 * HD + cc0 * 8);
            cp_async16(nk + cr1 * H2STB + cc1 * 16, ksrc + (size_t)cr1 * HD + cc1 * 8);
            cp_async16(nv + cr0 * H2STB + cc0 * 16, vsrc + (size_t)cr0 * HD + cc0 * 8);
            cp_async16(nv + cr1 * H2STB + cc1 * 16, vsrc + (size_t)cr1 * HD + cc1 * 8);
            cp_commit();
        }

        // ---- S = Q K^T ----
        float sfr[8][4];
        #pragma unroll
        for (int nb = 0; nb < 8; nb++)
            #pragma unroll
            for (int r = 0; r < 4; r++) sfr[nb][r] = 0.f;

        const uint32_t ks_lane = kbase + ks_lane_off;
        const uint32_t vs_lane = vbase + vs_lane_off;

        #pragma unroll
        for (int nbp = 0; nbp < 4; nbp++) {
            uint32_t fB[4][4];
            #pragma unroll
            for (int kk = 0; kk < 4; kk++)
                ldsm_x4(fB[kk][0], fB[kk][1], fB[kk][2], fB[kk][3],
                        ks_lane + nbp * 16 * H2STB + kk * 32);
            int nb = nbp * 2;
            #pragma unroll
            for (int kk = 0; kk < 4; kk++) {
                mma_f16(sfr[nb][0], sfr[nb][1], sfr[nb][2], sfr[nb][3],
                        qf[kk][0], qf[kk][1], qf[kk][2], qf[kk][3],
                        fB[kk][0], fB[kk][1]);
                mma_f16(sfr[nb+1][0], sfr[nb+1][1], sfr[nb+1][2], sfr[nb+1][3],
                        qf[kk][0], qf[kk][1], qf[kk][2], qf[kk][3],
                        fB[kk][2], fB[kk][3]);
            }
        }

        // ---- online softmax (fp32) ----
        float mt0 = m0, mt1 = m1;
        #pragma unroll
        for (int nb = 0; nb < 8; nb++) {
            mt0 = fmaxf(mt0, fmaxf(sfr[nb][0], sfr[nb][1]));
            mt1 = fmaxf(mt1, fmaxf(sfr[nb][2], sfr[nb][3]));
        }
        mt0 = fmaxf(mt0, __shfl_xor_sync(0xffffffff, mt0, 1));
        mt0 = fmaxf(mt0, __shfl_xor_sync(0xffffffff, mt0, 2));
        mt1 = fmaxf(mt1, __shfl_xor_sync(0xffffffff, mt1, 1));
        mt1 = fmaxf(mt1, __shfl_xor_sync(0xffffffff, mt1, 2));

        float c0 = __expf(m0 - mt0);
        float c1 = __expf(m1 - mt1);
        m0 = mt0; m1 = mt1;
        l0 *= c0; l1 *= c1;
        #pragma unroll
        for (int nb = 0; nb < 8; nb++) {
            o[nb][0] *= c0; o[nb][1] *= c0;
            o[nb][2] *= c1; o[nb][3] *= c1;
        }

        // ---- P = exp(S - m) -> half2 Ps ----
        {
            int r0 = (wid * 16 + qr) * H2ST;
            int r1 = r0 + 8 * H2ST;
            #pragma unroll
            for (int nb = 0; nb < 8; nb++) {
                float p0 = __expf(sfr[nb][0] - m0);
                float p1 = __expf(sfr[nb][1] - m0);
                float p2 = __expf(sfr[nb][2] - m1);
                float p3 = __expf(sfr[nb][3] - m1);
                l0 += p0 + p1;
                l1 += p2 + p3;
                Ps2[r0 + nb * 4 + qc] = f2h2(p0, p1);
                Ps2[r1 + nb * 4 + qc] = f2h2(p2, p3);
            }
        }
        __syncwarp();

        // ---- O += P V ----
        {
            uint32_t pf[4][4];
            #pragma unroll
            for (int kk = 0; kk < 4; kk++)
                ldsm_x4(pf[kk][0], pf[kk][1], pf[kk][2], pf[kk][3],
                        ps_lane + kk * 32);
            #pragma unroll
            for (int nbp = 0; nbp < 4; nbp++) {
                uint32_t vf[4][4];
                #pragma unroll
                for (int kk = 0; kk < 4; kk++)
                    ldsm_x4t(vf[kk][0], vf[kk][1], vf[kk][2], vf[kk][3],
                             vs_lane + kk * 16 * H2STB + nbp * 32);
                int nb = nbp * 2;
                #pragma unroll
                for (int kk = 0; kk < 4; kk++) {
                    mma_f16(o[nb][0], o[nb][1], o[nb][2], o[nb][3],
                            pf[kk][0], pf[kk][2], pf[kk][1], pf[kk][3],
                            vf[kk][0], vf[kk][1]);
                    mma_f16(o[nb+1][0], o[nb+1][1], o[nb+1][2], o[nb+1][3],
                            pf[kk][0], pf[kk][2], pf[kk][1], pf[kk][3],
                            vf[kk][2], vf[kk][3]);
                }
            }
        }
        __syncthreads();   // all reads of this buffer done before it is refilled
    }

    l0 += __shfl_xor_sync(0xffffffff, l0, 1);
    l0 += __shfl_xor_sync(0xffffffff, l0, 2);
    l1 += __shfl_xor_sync(0xffffffff, l1, 1);
    l1 += __shfl_xor_sync(0xffffffff, l1, 2);
    float inv0 = 1.f / l0;
    float inv1 = 1.f / l1;

    int row0 = q0 + wid * 16 + qr;
    #pragma unroll
    for (int nb = 0; nb < 8; nb++) {
        int col = h * HD + nb * 8 + 2 * qc;
        float2 w0, w1;
        w0.x = o[nb][0] * inv0; w0.y = o[nb][1] * inv0;
        w1.x = o[nb][2] * inv1; w1.y = o[nb][3] * inv1;
        *(float2*)&g_attn[(size_t)row0 * DIM + col] = w0;
        *(float2*)&g_attn[(size_t)(row0 + 8) * DIM + col] = w1;
    }
}

#define ATT_SMEM ((4 * KVBUF + 128 * H2ST) * 4)

// ---------------- launch ----------------
extern "C" void kernel_launch(void* const* d_in, const int* in_sizes, int n_in,
                              void* d_out, int out_size)
{
    const float* x      = (const float*)d_in[0];
    const float* cosb   = (const float*)d_in[1];
    const float* sinb   = (const float*)d_in[2];
    const float* w_qkv  = (const float*)d_in[3];
    const float* b_qkv  = (const float*)d_in[4];
    const float* w_proj = (const float*)d_in[5];
    const float* b_proj = (const float*)d_in[6];
    float* out = (float*)d_out;

    float *p_qkv, *p_attn;
    cudaGetSymbolAddress((void**)&p_qkv, g_qkv);
    cudaGetSymbolAddress((void**)&p_attn, g_attn);

    cudaFuncSetAttribute(attn_mma_kernel,
                         cudaFuncAttributeMaxDynamicSharedMemorySize, ATT_SMEM);

    // 1) QKV GEMM (tf32)
    {
        dim3 grid(QKV_N / GBN, NTOK / GBM);
        gemm_tf32_kernel<<<grid, 256>>>(x, w_qkv, b_qkv, p_qkv, NTOK, QKV_N, DIM);
    }
    // 2) RoPE + split (K/V -> fp16)
    {
        int total = NTOK * NHEADS * 32;
        rope_split_kernel<<<(total + 255) / 256, 256>>>(cosb, sinb);
    }
    // 3) attention (fp16 MMA, cp.async double-buffered)
    {
        dim3 grid(NTOK / ATT_BQ, NHEADS);
        attn_mma_kernel<<<grid, 256, ATT_SMEM>>>();
    }
    // 4) proj GEMM (tf32)
    {
        dim3 grid(DIM / GBN, NTOK / GBM);
        gemm_tf32_kernel<<<grid, 256>>>(p_attn, w_proj, b_proj, out, NTOK, DIM, DIM);
    }
}

// round 17
// speedup vs baseline: 1.1308x; 1.1308x over previous
#include <cuda_runtime.h>
#include <cuda_fp16.h>
#include <stdint.h>
#include <math.h>

#define NTOK 4096
#define DIM 1024
#define NHEADS 16
#define HD 64
#define QKV_N 3072
#define SCALE 0.125f   // 1/sqrt(64)

// ---------------- scratch (no allocations allowed) ----------------
__device__ float  g_qkv[NTOK * QKV_N];
__device__ float  g_Q[NHEADS * NTOK * HD];
__device__ __half g_Kh[NHEADS * NTOK * HD];
__device__ __half g_Vh[NHEADS * NTOK * HD];
__device__ float  g_attn[NTOK * DIM];

__device__ __forceinline__ uint32_t cvt_tf32(float x) {
    uint32_t r;
    asm("cvt.rna.tf32.f32 %0, %1;" : "=r"(r) : "f"(x));
    return r;
}

__device__ __forceinline__ uint32_t f2h2(float a, float b) {
    __half2 h = __floats2half2_rn(a, b);
    return *(uint32_t*)&h;
}

__device__ __forceinline__ void mma_tf32(float& c0, float& c1, float& c2, float& c3,
                                         uint32_t a0, uint32_t a1, uint32_t a2, uint32_t a3,
                                         uint32_t b0, uint32_t b1) {
    asm volatile(
        "mma.sync.aligned.m16n8k8.row.col.f32.tf32.tf32.f32 "
        "{%0,%1,%2,%3}, {%4,%5,%6,%7}, {%8,%9}, {%0,%1,%2,%3};"
        : "+f"(c0), "+f"(c1), "+f"(c2), "+f"(c3)
        : "r"(a0), "r"(a1), "r"(a2), "r"(a3), "r"(b0), "r"(b1));
}

__device__ __forceinline__ void mma_f16(float& c0, float& c1, float& c2, float& c3,
                                        uint32_t a0, uint32_t a1, uint32_t a2, uint32_t a3,
                                        uint32_t b0, uint32_t b1) {
    asm volatile(
        "mma.sync.aligned.m16n8k16.row.col.f32.f16.f16.f32 "
        "{%0,%1,%2,%3}, {%4,%5,%6,%7}, {%8,%9}, {%0,%1,%2,%3};"
        : "+f"(c0), "+f"(c1), "+f"(c2), "+f"(c3)
        : "r"(a0), "r"(a1), "r"(a2), "r"(a3), "r"(b0), "r"(b1));
}

__device__ __forceinline__ void ldsm_x4(uint32_t& r0, uint32_t& r1,
                                        uint32_t& r2, uint32_t& r3, uint32_t saddr) {
    asm volatile("ldmatrix.sync.aligned.m8n8.x4.shared.b16 {%0,%1,%2,%3}, [%4];"
                 : "=r"(r0), "=r"(r1), "=r"(r2), "=r"(r3) : "r"(saddr));
}

__device__ __forceinline__ void ldsm_x4t(uint32_t& r0, uint32_t& r1,
                                         uint32_t& r2, uint32_t& r3, uint32_t saddr) {
    asm volatile("ldmatrix.sync.aligned.m8n8.x4.trans.shared.b16 {%0,%1,%2,%3}, [%4];"
                 : "=r"(r0), "=r"(r1), "=r"(r2), "=r"(r3) : "r"(saddr));
}

__device__ __forceinline__ void cp_async16(uint32_t saddr, const void* gptr) {
    asm volatile("cp.async.cg.shared.global [%0], [%1], 16;"
                 :: "r"(saddr), "l"(gptr));
}
__device__ __forceinline__ void cp_commit() {
    asm volatile("cp.async.commit_group;");
}
__device__ __forceinline__ void cp_wait0() {
    asm volatile("cp.async.wait_group 0;");
}

// ---------------- tf32 MMA GEMM with register-prefetch pipeline (85us) ------
#define GBM 128
#define GBN 128
#define GBK 16
#define GST 136

__global__ __launch_bounds__(256, 2) void gemm_tf32_kernel(
    const float* __restrict__ A, const float* __restrict__ B,
    const float* __restrict__ bias, float* __restrict__ C,
    int M, int N, int K)
{
    __shared__ float Ast[GBK][GST];
    __shared__ float Bs[GBK][GST];

    const int tid = threadIdx.x;
    const int wid = tid >> 5;
    const int lane = tid & 31;
    const int qr = lane >> 2;
    const int qc = lane & 3;
    const int wm = wid >> 2;
    const int wn = wid & 3;
    const int rowBase = blockIdx.y * GBM;
    const int colBase = blockIdx.x * GBN;

    int ar[2], ac[2], br[2], bc[2];
    #pragma unroll
    for (int i = 0; i < 2; i++) {
        int v = tid + i * 256;
        ar[i] = v >> 2;  ac[i] = (v & 3) * 4;
        br[i] = v >> 5;  bc[i] = (v & 31) * 4;
    }

    float acc[4][4][4];
    #pragma unroll
    for (int mi = 0; mi < 4; mi++)
        #pragma unroll
        for (int ni = 0; ni < 4; ni++)
            #pragma unroll
            for (int r = 0; r < 4; r++) acc[mi][ni][r] = 0.f;

    float4 pa[2], pb[2];
    #pragma unroll
    for (int i = 0; i < 2; i++) {
        pa[i] = *(const float4*)&A[(size_t)(rowBase + ar[i]) * K + ac[i]];
        pb[i] = *(const float4*)&B[(size_t)br[i] * N + colBase + bc[i]];
    }

    for (int k0 = 0; k0 < K; k0 += GBK) {
        #pragma unroll
        for (int i = 0; i < 2; i++) {
            Ast[ac[i] + 0][ar[i]] = __uint_as_float(cvt_tf32(pa[i].x));
            Ast[ac[i] + 1][ar[i]] = __uint_as_float(cvt_tf32(pa[i].y));
            Ast[ac[i] + 2][ar[i]] = __uint_as_float(cvt_tf32(pa[i].z));
            Ast[ac[i] + 3][ar[i]] = __uint_as_float(cvt_tf32(pa[i].w));
            float4 g;
            g.x = __uint_as_float(cvt_tf32(pb[i].x));
            g.y = __uint_as_float(cvt_tf32(pb[i].y));
            g.z = __uint_as_float(cvt_tf32(pb[i].z));
            g.w = __uint_as_float(cvt_tf32(pb[i].w));
            *(float4*)&Bs[br[i]][bc[i]] = g;
        }
        __syncthreads();

        if (k0 + GBK < K) {
            #pragma unroll
            for (int i = 0; i < 2; i++) {
                pa[i] = *(const float4*)&A[(size_t)(rowBase + ar[i]) * K + (k0 + GBK) + ac[i]];
                pb[i] = *(const float4*)&B[(size_t)(k0 + GBK + br[i]) * N + colBase + bc[i]];
            }
        }

        #pragma unroll
        for (int kk = 0; kk < 2; kk++) {
            uint32_t af[4][4], bf[4][2];
            #pragma unroll
            for (int mi = 0; mi < 4; mi++) {
                int m = wm * 64 + mi * 16;
                af[mi][0] = __float_as_uint(Ast[kk * 8 + qc]    [m + qr]);
                af[mi][1] = __float_as_uint(Ast[kk * 8 + qc]    [m + qr + 8]);
                af[mi][2] = __float_as_uint(Ast[kk * 8 + qc + 4][m + qr]);
                af[mi][3] = __float_as_uint(Ast[kk * 8 + qc + 4][m + qr + 8]);
            }
            #pragma unroll
            for (int ni = 0; ni < 4; ni++) {
                int n = wn * 32 + ni * 8;
                bf[ni][0] = __float_as_uint(Bs[kk * 8 + qc]    [n + qr]);
                bf[ni][1] = __float_as_uint(Bs[kk * 8 + qc + 4][n + qr]);
            }
            #pragma unroll
            for (int mi = 0; mi < 4; mi++)
                #pragma unroll
                for (int ni = 0; ni < 4; ni++)
                    mma_tf32(acc[mi][ni][0], acc[mi][ni][1], acc[mi][ni][2], acc[mi][ni][3],
                             af[mi][0], af[mi][1], af[mi][2], af[mi][3],
                             bf[ni][0], bf[ni][1]);
        }
        __syncthreads();
    }

    #pragma unroll
    for (int mi = 0; mi < 4; mi++) {
        int m = rowBase + wm * 64 + mi * 16;
        #pragma unroll
        for (int ni = 0; ni < 4; ni++) {
            int n = colBase + wn * 32 + ni * 8 + 2 * qc;
            float bx = bias[n], by = bias[n + 1];
            float2 w0, w1;
            w0.x = acc[mi][ni][0] + bx;  w0.y = acc[mi][ni][1] + by;
            w1.x = acc[mi][ni][2] + bx;  w1.y = acc[mi][ni][3] + by;
            *(float2*)&C[(size_t)(m + qr) * N + n] = w0;
            *(float2*)&C[(size_t)(m + qr + 8) * N + n] = w1;
        }
    }
}

// ---------------- RoPE + split: Q fp32, K/V fp16 ----------------
__global__ void rope_split_kernel(const float* __restrict__ cosb,
                                  const float* __restrict__ sinb)
{
    int idx = blockIdx.x * blockDim.x + threadIdx.x;
    if (idx >= NTOK * NHEADS * 32) return;
    int d = idx & 31;
    int h = (idx >> 5) & 15;
    int n = idx >> 9;

    const float* base = g_qkv + (size_t)n * QKV_N;
    float c = cosb[n * 32 + d];
    float s = sinb[n * 32 + d];

    size_t ho = ((size_t)h * NTOK + n) * HD;

    float x1 = base[h * HD + d];
    float x2 = base[h * HD + d + 32];
    g_Q[ho + d]      = x1 * c - x2 * s;
    g_Q[ho + d + 32] = x2 * c + x1 * s;

    float y1 = base[DIM + h * HD + d];
    float y2 = base[DIM + h * HD + d + 32];
    g_Kh[ho + d]      = __float2half(y1 * c - y2 * s);
    g_Kh[ho + d + 32] = __float2half(y2 * c + y1 * s);

    g_Vh[ho + d]      = __float2half(base[2 * DIM + h * HD + d]);
    g_Vh[ho + d + 32] = __float2half(base[2 * DIM + h * HD + d + 32]);
}

// ---------------- flash attention: fp16 mma, P kept in registers ------------
// Key identity: the S C-fragment layout (cols 2qc,2qc+1 per n8-block) IS the
// m16n8k16 A-fragment layout (k-cols 2qc,2qc+1 per k16-block), so PV A-frags
// are built from exp'd S fragments with f2h2 — no smem roundtrip for P.
#define ATT_BQ 128
#define H2ST 36            // half2 words per row (32 data + 4 pad)
#define H2STB 144          // bytes
#define KVBUF (64 * H2ST)  // words per K or V buffer

__global__ __launch_bounds__(256, 2) void attn_mma_kernel()
{
    extern __shared__ uint32_t sm2[];
    // [buf0: K,V][buf1: K,V]

    const int tid = threadIdx.x;
    const int h = blockIdx.y;
    const int q0 = blockIdx.x * ATT_BQ;
    const int wid = tid >> 5;
    const int lane = tid & 31;
    const int qr = lane >> 2;
    const int qc = lane & 3;

    const uint32_t sm_base = (uint32_t)__cvta_generic_to_shared(sm2);

    const uint32_t ks_lane_off = (((lane >> 4) & 1) * 8 + (lane & 7)) * H2STB
                               + ((lane >> 3) & 1) * 16;
    const uint32_t vs_lane_off = (((lane >> 3) & 1) * 8 + (lane & 7)) * H2STB
                               + ((lane >> 4) & 1) * 16;

    // cp.async per-thread chunk coords: 512 16B-chunks per matrix, 2/thread
    const int cv0 = tid, cv1 = tid + 256;
    const int cr0 = cv0 >> 3, cc0 = cv0 & 7;
    const int cr1 = cv1 >> 3, cc1 = cv1 & 7;

    const float* qbase = g_Q + ((size_t)h * NTOK + q0 + wid * 16) * HD;
    uint32_t qf[4][4];
    #pragma unroll
    for (int kk = 0; kk < 4; kk++) {
        int k0 = kk * 16 + 2 * qc;
        qf[kk][0] = f2h2(qbase[(size_t)qr       * HD + k0]     * SCALE,
                         qbase[(size_t)qr       * HD + k0 + 1] * SCALE);
        qf[kk][1] = f2h2(qbase[(size_t)(qr + 8) * HD + k0]     * SCALE,
                         qbase[(size_t)(qr + 8) * HD + k0 + 1] * SCALE);
        qf[kk][2] = f2h2(qbase[(size_t)qr       * HD + k0 + 8] * SCALE,
                         qbase[(size_t)qr       * HD + k0 + 9] * SCALE);
        qf[kk][3] = f2h2(qbase[(size_t)(qr + 8) * HD + k0 + 8] * SCALE,
                         qbase[(size_t)(qr + 8) * HD + k0 + 9] * SCALE);
    }

    float m0 = -1e30f, m1 = -1e30f, l0 = 0.f, l1 = 0.f;
    float o[8][4];
    #pragma unroll
    for (int nb = 0; nb < 8; nb++)
        #pragma unroll
        for (int r = 0; r < 4; r++) o[nb][r] = 0.f;

    const __half* kb = g_Kh + (size_t)h * NTOK * HD;
    const __half* vb = g_Vh + (size_t)h * NTOK * HD;

    // prefetch tile 0 into buffer 0
    {
        uint32_t kdst = sm_base;
        uint32_t vdst = sm_base + KVBUF * 4;
        cp_async16(kdst + cr0 * H2STB + cc0 * 16, kb + (size_t)cr0 * HD + cc0 * 8);
        cp_async16(kdst + cr1 * H2STB + cc1 * 16, kb + (size_t)cr1 * HD + cc1 * 8);
        cp_async16(vdst + cr0 * H2STB + cc0 * 16, vb + (size_t)cr0 * HD + cc0 * 8);
        cp_async16(vdst + cr1 * H2STB + cc1 * 16, vb + (size_t)cr1 * HD + cc1 * 8);
        cp_commit();
    }

    #pragma unroll 1
    for (int t = 0; t < NTOK; t += 64) {
        const int buf = (t >> 6) & 1;
        const uint32_t kbase = sm_base + buf * 2 * KVBUF * 4;
        const uint32_t vbase = kbase + KVBUF * 4;

        cp_wait0();
        __syncthreads();

        // prefetch next tile into the other buffer
        if (t + 64 < NTOK) {
            const uint32_t nk = sm_base + (buf ^ 1) * 2 * KVBUF * 4;
            const uint32_t nv = nk + KVBUF * 4;
            const __half* ksrc = kb + (size_t)(t + 64) * HD;
            const __half* vsrc = vb + (size_t)(t + 64) * HD;
            cp_async16(nk + cr0 * H2STB + cc0 * 16, ksrc + (size_t)cr0 * HD + cc0 * 8);
            cp_async16(nk + cr1 * H2STB + cc1 * 16, ksrc + (size_t)cr1 * HD + cc1 * 8);
            cp_async16(nv + cr0 * H2STB + cc0 * 16, vsrc + (size_t)cr0 * HD + cc0 * 8);
            cp_async16(nv + cr1 * H2STB + cc1 * 16, vsrc + (size_t)cr1 * HD + cc1 * 8);
            cp_commit();
        }

        // ---- S = Q K^T ----
        float sfr[8][4];
        #pragma unroll
        for (int nb = 0; nb < 8; nb++)
            #pragma unroll
            for (int r = 0; r < 4; r++) sfr[nb][r] = 0.f;

        const uint32_t ks_lane = kbase + ks_lane_off;
        const uint32_t vs_lane = vbase + vs_lane_off;

        #pragma unroll
        for (int nbp = 0; nbp < 4; nbp++) {
            uint32_t fB[4][4];
            #pragma unroll
            for (int kk = 0; kk < 4; kk++)
                ldsm_x4(fB[kk][0], fB[kk][1], fB[kk][2], fB[kk][3],
                        ks_lane + nbp * 16 * H2STB + kk * 32);
            int nb = nbp * 2;
            #pragma unroll
            for (int kk = 0; kk < 4; kk++) {
                mma_f16(sfr[nb][0], sfr[nb][1], sfr[nb][2], sfr[nb][3],
                        qf[kk][0], qf[kk][1], qf[kk][2], qf[kk][3],
                        fB[kk][0], fB[kk][1]);
                mma_f16(sfr[nb+1][0], sfr[nb+1][1], sfr[nb+1][2], sfr[nb+1][3],
                        qf[kk][0], qf[kk][1], qf[kk][2], qf[kk][3],
                        fB[kk][2], fB[kk][3]);
            }
        }

        // ---- online softmax (fp32) ----
        float mt0 = m0, mt1 = m1;
        #pragma unroll
        for (int nb = 0; nb < 8; nb++) {
            mt0 = fmaxf(mt0, fmaxf(sfr[nb][0], sfr[nb][1]));
            mt1 = fmaxf(mt1, fmaxf(sfr[nb][2], sfr[nb][3]));
        }
        mt0 = fmaxf(mt0, __shfl_xor_sync(0xffffffff, mt0, 1));
        mt0 = fmaxf(mt0, __shfl_xor_sync(0xffffffff, mt0, 2));
        mt1 = fmaxf(mt1, __shfl_xor_sync(0xffffffff, mt1, 1));
        mt1 = fmaxf(mt1, __shfl_xor_sync(0xffffffff, mt1, 2));

        float c0 = __expf(m0 - mt0);
        float c1 = __expf(m1 - mt1);
        m0 = mt0; m1 = mt1;
        l0 *= c0; l1 *= c1;
        #pragma unroll
        for (int nb = 0; nb < 8; nb++) {
            o[nb][0] *= c0; o[nb][1] *= c0;
            o[nb][2] *= c1; o[nb][3] *= c1;
        }

        // ---- P = exp(S - m) in registers (overwrite sfr) ----
        #pragma unroll
        for (int nb = 0; nb < 8; nb++) {
            sfr[nb][0] = __expf(sfr[nb][0] - m0);
            sfr[nb][1] = __expf(sfr[nb][1] - m0);
            sfr[nb][2] = __expf(sfr[nb][2] - m1);
            sfr[nb][3] = __expf(sfr[nb][3] - m1);
            l0 += sfr[nb][0] + sfr[nb][1];
            l1 += sfr[nb][2] + sfr[nb][3];
        }

        // ---- PV A-frags directly from exp'd C-frags (no smem roundtrip) ----
        uint32_t pf[4][4];
        #pragma unroll
        for (int kk = 0; kk < 4; kk++) {
            pf[kk][0] = f2h2(sfr[2*kk][0],     sfr[2*kk][1]);       // (qr,   k 2qc..+1)
            pf[kk][1] = f2h2(sfr[2*kk][2],     sfr[2*kk][3]);       // (qr+8, k 2qc..+1)
            pf[kk][2] = f2h2(sfr[2*kk + 1][0], sfr[2*kk + 1][1]);   // (qr,   k 2qc+8..)
            pf[kk][3] = f2h2(sfr[2*kk + 1][2], sfr[2*kk + 1][3]);   // (qr+8, k 2qc+8..)
        }

        // ---- O += P V ----
        #pragma unroll
        for (int nbp = 0; nbp < 4; nbp++) {
            uint32_t vf[4][4];
            #pragma unroll
            for (int kk = 0; kk < 4; kk++)
                ldsm_x4t(vf[kk][0], vf[kk][1], vf[kk][2], vf[kk][3],
                         vs_lane + kk * 16 * H2STB + nbp * 32);
            int nb = nbp * 2;
            #pragma unroll
            for (int kk = 0; kk < 4; kk++) {
                mma_f16(o[nb][0], o[nb][1], o[nb][2], o[nb][3],
                        pf[kk][0], pf[kk][1], pf[kk][2], pf[kk][3],
                        vf[kk][0], vf[kk][1]);
                mma_f16(o[nb+1][0], o[nb+1][1], o[nb+1][2], o[nb+1][3],
                        pf[kk][0], pf[kk][1], pf[kk][2], pf[kk][3],
                        vf[kk][2], vf[kk][3]);
            }
        }
        __syncthreads();   // all reads of this buffer done before refill
    }

    l0 += __shfl_xor_sync(0xffffffff, l0, 1);
    l0 += __shfl_xor_sync(0xffffffff, l0, 2);
    l1 += __shfl_xor_sync(0xffffffff, l1, 1);
    l1 += __shfl_xor_sync(0xffffffff, l1, 2);
    float inv0 = 1.f / l0;
    float inv1 = 1.f / l1;

    int row0 = q0 + wid * 16 + qr;
    #pragma unroll
    for (int nb = 0; nb < 8; nb++) {
        int col = h * HD + nb * 8 + 2 * qc;
        float2 w0, w1;
        w0.x = o[nb][0] * inv0; w0.y = o[nb][1] * inv0;
        w1.x = o[nb][2] * inv1; w1.y = o[nb][3] * inv1;
        *(float2*)&g_attn[(size_t)row0 * DIM + col] = w0;
        *(float2*)&g_attn[(size_t)(row0 + 8) * DIM + col] = w1;
    }
}

#define ATT_SMEM (4 * KVBUF * 4)

// ---------------- launch ----------------
extern "C" void kernel_launch(void* const* d_in, const int* in_sizes, int n_in,
                              void* d_out, int out_size)
{
    const float* x      = (const float*)d_in[0];
    const float* cosb   = (const float*)d_in[1];
    const float* sinb   = (const float*)d_in[2];
    const float* w_qkv  = (const float*)d_in[3];
    const float* b_qkv  = (const float*)d_in[4];
    const float* w_proj = (const float*)d_in[5];
    const float* b_proj = (const float*)d_in[6];
    float* out = (float*)d_out;

    float *p_qkv, *p_attn;
    cudaGetSymbolAddress((void**)&p_qkv, g_qkv);
    cudaGetSymbolAddress((void**)&p_attn, g_attn);

    cudaFuncSetAttribute(attn_mma_kernel,
                         cudaFuncAttributeMaxDynamicSharedMemorySize, ATT_SMEM);

    // 1) QKV GEMM (tf32)
    {
        dim3 grid(QKV_N / GBN, NTOK / GBM);
        gemm_tf32_kernel<<<grid, 256>>>(x, w_qkv, b_qkv, p_qkv, NTOK, QKV_N, DIM);
    }
    // 2) RoPE + split (K/V -> fp16)
    {
        int total = NTOK * NHEADS * 32;
        rope_split_kernel<<<(total + 255) / 256, 256>>>(cosb, sinb);
    }
    // 3) attention (fp16 MMA, P in registers, 2 CTAs/SM)
    {
        dim3 grid(NTOK / ATT_BQ, NHEADS);
        attn_mma_kernel<<<grid, 256, ATT_SMEM>>>();
    }
    // 4) proj GEMM (tf32)
    {
        dim3 grid(DIM / GBN, NTOK / GBM);
        gemm_tf32_kernel<<<grid, 256>>>(p_attn, w_proj, b_proj, out, NTOK, DIM, DIM);
    }
}